// round 1
// baseline (speedup 1.0000x reference)
#include <cuda_runtime.h>
#include <cuda_bf16.h>
#include <cstdint>

#define NUM_EXPERTS 16
#define NPAIR 8
#define DIM 1024
#define BLOCK_TOKENS 512
#define THREADS 512
#define DC 32                 // dims per staged chunk
#define NCHUNK (DIM / DC)     // 32
#define PITCH 36              // floats per token row in smem tile (conflict-free, 16B aligned)

// shared memory layout (in floats)
#define WS_FLOATS (NPAIR * DIM * 2)      // 16384 (64KB), pair-major [pair][d][2]
#define BS_OFF    WS_FLOATS              // bias, 16 floats (padded to 32)
#define X0_OFF    (WS_FLOATS + 32)
#define XBUF_FLOATS (BLOCK_TOKENS * PITCH)  // 18432
#define X1_OFF    (X0_OFF + XBUF_FLOATS)
#define SMEM_FLOATS (X1_OFF + XBUF_FLOATS)  // 53280 floats
#define SMEM_BYTES  (SMEM_FLOATS * 4)       // 213120 B

__device__ __forceinline__ void ffma2(unsigned long long& acc,
                                      unsigned long long a,
                                      unsigned long long b) {
    asm("fma.rn.f32x2 %0, %1, %2, %0;" : "+l"(acc) : "l"(a), "l"(b));
}

__device__ __forceinline__ unsigned long long pack2(float v) {
    unsigned long long r;
    asm("mov.b64 %0, {%1, %1};" : "=l"(r) : "r"(__float_as_uint(v)));
    return r;
}

__global__ __launch_bounds__(THREADS, 1)
void gating_kernel(const float* __restrict__ x,
                   const float* __restrict__ W,
                   const float* __restrict__ b,
                   float* __restrict__ out,
                   int T /* total tokens */) {
    extern __shared__ float smem[];
    float* W_s = smem;
    float* b_s = smem + BS_OFF;

    const int tid = threadIdx.x;
    const int tok_base = blockIdx.x * BLOCK_TOKENS;
    const float* x_blk = x + (size_t)tok_base * DIM;

    const uint32_t smem_u32 = (uint32_t)__cvta_generic_to_shared(smem);

    // Per-thread staging geometry (loop-invariant): 8 float4s per chunk.
    // float4 index i = tid + k*THREADS; token = i>>3 (8 float4 per 32-dim row), j = i&7.
    // Prefetch chunk 0 into buffer 0.
    {
        const uint32_t dst_base = smem_u32 + X0_OFF * 4;
#pragma unroll
        for (int k = 0; k < 8; k++) {
            int i = tid + k * THREADS;
            int t = i >> 3;
            int j = i & 7;
            const float* src = x_blk + (size_t)t * DIM + j * 4;
            uint32_t dst = dst_base + (uint32_t)(t * PITCH + j * 4) * 4;
            asm volatile("cp.async.cg.shared.global [%0], [%1], 16;\n"
                         :: "r"(dst), "l"(src));
        }
        asm volatile("cp.async.commit_group;\n" ::: "memory");
    }

    // Repack W into pair-major [pair][d][2] while chunk 0 is in flight.
    for (int i = tid; i < NUM_EXPERTS * DIM; i += THREADS) {
        int e = i >> 10;
        int d = i & (DIM - 1);
        W_s[((e >> 1) * DIM + d) * 2 + (e & 1)] = W[i];
    }
    if (tid < NUM_EXPERTS) b_s[tid] = b[tid];

    asm volatile("cp.async.wait_group 0;\n" ::: "memory");
    __syncthreads();

    unsigned long long acc[NPAIR];
#pragma unroll
    for (int p = 0; p < NPAIR; p++) acc[p] = 0ULL;

    int buf = 0;
    for (int c = 0; c < NCHUNK; c++) {
        // Prefetch next chunk into the other buffer.
        if (c + 1 < NCHUNK) {
            const uint32_t dst_base = smem_u32 + (buf ? X0_OFF : X1_OFF) * 4;
            const int dim0 = (c + 1) * DC;
#pragma unroll
            for (int k = 0; k < 8; k++) {
                int i = tid + k * THREADS;
                int t = i >> 3;
                int j = i & 7;
                const float* src = x_blk + (size_t)t * DIM + dim0 + j * 4;
                uint32_t dst = dst_base + (uint32_t)(t * PITCH + j * 4) * 4;
                asm volatile("cp.async.cg.shared.global [%0], [%1], 16;\n"
                             :: "r"(dst), "l"(src));
            }
        }
        asm volatile("cp.async.commit_group;\n" ::: "memory");

        // Compute on current buffer: thread owns token `tid` of this block.
        const float* xrow = smem + (buf ? X1_OFF : X0_OFF) + tid * PITCH;
        const uint32_t wbase = smem_u32 + (uint32_t)(c * DC * 2) * 4;
#pragma unroll
        for (int j = 0; j < DC / 4; j++) {
            float4 xv = *reinterpret_cast<const float4*>(xrow + j * 4);
            unsigned long long xx0 = pack2(xv.x);
            unsigned long long xx1 = pack2(xv.y);
            unsigned long long xx2 = pack2(xv.z);
            unsigned long long xx3 = pack2(xv.w);
            const uint32_t wj = wbase + (uint32_t)(j * 4 * 2) * 4;
#pragma unroll
            for (int p = 0; p < NPAIR; p++) {
                unsigned long long w0, w1, w2, w3;
                uint32_t a = wj + (uint32_t)(p * DIM * 2) * 4;
                asm("ld.shared.v2.b64 {%0, %1}, [%2];"
                    : "=l"(w0), "=l"(w1) : "r"(a));
                asm("ld.shared.v2.b64 {%0, %1}, [%2];"
                    : "=l"(w2), "=l"(w3) : "r"(a + 16));
                ffma2(acc[p], xx0, w0);
                ffma2(acc[p], xx1, w1);
                ffma2(acc[p], xx2, w2);
                ffma2(acc[p], xx3, w3);
            }
        }

        asm volatile("cp.async.wait_group 0;\n" ::: "memory");
        __syncthreads();
        buf ^= 1;
    }

    // ---- epilogue: bias, softmax, top-2, scatter ----
    float logit[NUM_EXPERTS];
#pragma unroll
    for (int p = 0; p < NPAIR; p++) {
        logit[2 * p]     = __uint_as_float((uint32_t)acc[p]) + b_s[2 * p];
        logit[2 * p + 1] = __uint_as_float((uint32_t)(acc[p] >> 32)) + b_s[2 * p + 1];
    }

    float m = logit[0];
#pragma unroll
    for (int e = 1; e < NUM_EXPERTS; e++) m = fmaxf(m, logit[e]);

    float sum = 0.0f;
#pragma unroll
    for (int e = 0; e < NUM_EXPERTS; e++) {
        float w = __expf(logit[e] - m);
        logit[e] = w;
        sum += w;
    }
    const float inv = __fdividef(1.0f, sum);
#pragma unroll
    for (int e = 0; e < NUM_EXPERTS; e++) logit[e] *= inv;

    // top-2 (strict > keeps lowest index on ties, matching jax top_k)
    float v1 = -1.0f, v2 = -1.0f;
    int i1 = 0, i2 = 0;
#pragma unroll
    for (int e = 0; e < NUM_EXPERTS; e++) {
        float w = logit[e];
        if (w > v1) { v2 = v1; i2 = i1; v1 = w; i1 = e; }
        else if (w > v2) { v2 = w; i2 = e; }
    }

    const size_t t = (size_t)tok_base + tid;
    float* outg = out;                                   // gated  [E, T]
    float* outw = out + (size_t)NUM_EXPERTS * T;         // weights[E, T]
#pragma unroll
    for (int e = 0; e < NUM_EXPERTS; e++) {
        float g = (e == i1) ? v1 : ((e == i2) ? v2 : 0.0f);
        outg[(size_t)e * T + t] = g;
        outw[(size_t)e * T + t] = logit[e];
    }
}

extern "C" void kernel_launch(void* const* d_in, const int* in_sizes, int n_in,
                              void* d_out, int out_size) {
    const float* x = (const float*)d_in[0];
    const float* W = (const float*)d_in[1];
    const float* b = (const float*)d_in[2];
    float* out = (float*)d_out;

    const int T = in_sizes[0] / DIM;           // 65536 tokens
    const int grid = T / BLOCK_TOKENS;         // 128 blocks

    cudaFuncSetAttribute(gating_kernel,
                         cudaFuncAttributeMaxDynamicSharedMemorySize, SMEM_BYTES);
    gating_kernel<<<grid, THREADS, SMEM_BYTES>>>(x, W, b, out, T);
}

// round 2
// speedup vs baseline: 1.0009x; 1.0009x over previous
#include <cuda_runtime.h>
#include <cuda_bf16.h>
#include <cstdint>

#define NUM_EXPERTS 16
#define NPAIR 8
#define DIM 1024
#define BLOCK_TOKENS 512
#define THREADS 512
#define DC 32                 // dims per staged chunk
#define NCHUNK (DIM / DC)     // 32
#define PITCH 36              // floats per token row in smem tile (conflict-free, 16B aligned)

// shared memory layout (in floats)
#define WS_FLOATS (NPAIR * DIM * 2)      // 16384 (64KB), pair-major [pair][d][2]
#define BS_OFF    WS_FLOATS              // bias, 16 floats (padded to 32)
#define X0_OFF    (WS_FLOATS + 32)
#define XBUF_FLOATS (BLOCK_TOKENS * PITCH)  // 18432
#define X1_OFF    (X0_OFF + XBUF_FLOATS)
#define SMEM_FLOATS (X1_OFF + XBUF_FLOATS)  // 53280 floats
#define SMEM_BYTES  (SMEM_FLOATS * 4)       // 213120 B

__device__ __forceinline__ void ffma2(unsigned long long& acc,
                                      unsigned long long a,
                                      unsigned long long b) {
    asm("fma.rn.f32x2 %0, %1, %2, %0;" : "+l"(acc) : "l"(a), "l"(b));
}

__device__ __forceinline__ unsigned long long pack2(float v) {
    unsigned long long r;
    asm("mov.b64 %0, {%1, %1};" : "=l"(r) : "r"(__float_as_uint(v)));
    return r;
}

__global__ __launch_bounds__(THREADS, 1)
void gating_kernel(const float* __restrict__ x,
                   const float* __restrict__ W,
                   const float* __restrict__ b,
                   float* __restrict__ out,
                   int T /* total tokens */) {
    extern __shared__ float smem[];
    float* W_s = smem;
    float* b_s = smem + BS_OFF;

    const int tid = threadIdx.x;
    const int tok_base = blockIdx.x * BLOCK_TOKENS;
    const float* x_blk = x + (size_t)tok_base * DIM;

    const uint32_t smem_u32 = (uint32_t)__cvta_generic_to_shared(smem);

    // Per-thread staging geometry (loop-invariant): 8 float4s per chunk.
    // float4 index i = tid + k*THREADS; token = i>>3 (8 float4 per 32-dim row), j = i&7.
    // Prefetch chunk 0 into buffer 0.
    {
        const uint32_t dst_base = smem_u32 + X0_OFF * 4;
#pragma unroll
        for (int k = 0; k < 8; k++) {
            int i = tid + k * THREADS;
            int t = i >> 3;
            int j = i & 7;
            const float* src = x_blk + (size_t)t * DIM + j * 4;
            uint32_t dst = dst_base + (uint32_t)(t * PITCH + j * 4) * 4;
            asm volatile("cp.async.cg.shared.global [%0], [%1], 16;\n"
                         :: "r"(dst), "l"(src));
        }
        asm volatile("cp.async.commit_group;\n" ::: "memory");
    }

    // Repack W into pair-major [pair][d][2] while chunk 0 is in flight.
    for (int i = tid; i < NUM_EXPERTS * DIM; i += THREADS) {
        int e = i >> 10;
        int d = i & (DIM - 1);
        W_s[((e >> 1) * DIM + d) * 2 + (e & 1)] = W[i];
    }
    if (tid < NUM_EXPERTS) b_s[tid] = b[tid];

    asm volatile("cp.async.wait_group 0;\n" ::: "memory");
    __syncthreads();

    unsigned long long acc[NPAIR];
#pragma unroll
    for (int p = 0; p < NPAIR; p++) acc[p] = 0ULL;

    int buf = 0;
    for (int c = 0; c < NCHUNK; c++) {
        // Prefetch next chunk into the other buffer.
        if (c + 1 < NCHUNK) {
            const uint32_t dst_base = smem_u32 + (buf ? X0_OFF : X1_OFF) * 4;
            const int dim0 = (c + 1) * DC;
#pragma unroll
            for (int k = 0; k < 8; k++) {
                int i = tid + k * THREADS;
                int t = i >> 3;
                int j = i & 7;
                const float* src = x_blk + (size_t)t * DIM + dim0 + j * 4;
                uint32_t dst = dst_base + (uint32_t)(t * PITCH + j * 4) * 4;
                asm volatile("cp.async.cg.shared.global [%0], [%1], 16;\n"
                             :: "r"(dst), "l"(src));
            }
        }
        asm volatile("cp.async.commit_group;\n" ::: "memory");

        // Compute on current buffer: thread owns token `tid` of this block.
        const float* xrow = smem + (buf ? X1_OFF : X0_OFF) + tid * PITCH;
        const uint32_t wbase = smem_u32 + (uint32_t)(c * DC * 2) * 4;
#pragma unroll
        for (int j = 0; j < DC / 4; j++) {
            float4 xv = *reinterpret_cast<const float4*>(xrow + j * 4);
            unsigned long long xx0 = pack2(xv.x);
            unsigned long long xx1 = pack2(xv.y);
            unsigned long long xx2 = pack2(xv.z);
            unsigned long long xx3 = pack2(xv.w);
            const uint32_t wj = wbase + (uint32_t)(j * 4 * 2) * 4;
#pragma unroll
            for (int p = 0; p < NPAIR; p++) {
                unsigned long long w0, w1, w2, w3;
                uint32_t a = wj + (uint32_t)(p * DIM * 2) * 4;
                asm("ld.shared.v2.b64 {%0, %1}, [%2];"
                    : "=l"(w0), "=l"(w1) : "r"(a));
                asm("ld.shared.v2.b64 {%0, %1}, [%2];"
                    : "=l"(w2), "=l"(w3) : "r"(a + 16));
                ffma2(acc[p], xx0, w0);
                ffma2(acc[p], xx1, w1);
                ffma2(acc[p], xx2, w2);
                ffma2(acc[p], xx3, w3);
            }
        }

        asm volatile("cp.async.wait_group 0;\n" ::: "memory");
        __syncthreads();
        buf ^= 1;
    }

    // ---- epilogue: bias, softmax, top-2, scatter ----
    float logit[NUM_EXPERTS];
#pragma unroll
    for (int p = 0; p < NPAIR; p++) {
        logit[2 * p]     = __uint_as_float((uint32_t)acc[p]) + b_s[2 * p];
        logit[2 * p + 1] = __uint_as_float((uint32_t)(acc[p] >> 32)) + b_s[2 * p + 1];
    }

    float m = logit[0];
#pragma unroll
    for (int e = 1; e < NUM_EXPERTS; e++) m = fmaxf(m, logit[e]);

    float sum = 0.0f;
#pragma unroll
    for (int e = 0; e < NUM_EXPERTS; e++) {
        float w = __expf(logit[e] - m);
        logit[e] = w;
        sum += w;
    }
    const float inv = __fdividef(1.0f, sum);
#pragma unroll
    for (int e = 0; e < NUM_EXPERTS; e++) logit[e] *= inv;

    // top-2 (strict > keeps lowest index on ties, matching jax top_k)
    float v1 = -1.0f, v2 = -1.0f;
    int i1 = 0, i2 = 0;
#pragma unroll
    for (int e = 0; e < NUM_EXPERTS; e++) {
        float w = logit[e];
        if (w > v1) { v2 = v1; i2 = i1; v1 = w; i1 = e; }
        else if (w > v2) { v2 = w; i2 = e; }
    }

    const size_t t = (size_t)tok_base + tid;
    float* outg = out;                                   // gated  [E, T]
    float* outw = out + (size_t)NUM_EXPERTS * T;         // weights[E, T]
#pragma unroll
    for (int e = 0; e < NUM_EXPERTS; e++) {
        float g = (e == i1) ? v1 : ((e == i2) ? v2 : 0.0f);
        outg[(size_t)e * T + t] = g;
        outw[(size_t)e * T + t] = logit[e];
    }
}

extern "C" void kernel_launch(void* const* d_in, const int* in_sizes, int n_in,
                              void* d_out, int out_size) {
    const float* x = (const float*)d_in[0];
    const float* W = (const float*)d_in[1];
    const float* b = (const float*)d_in[2];
    float* out = (float*)d_out;

    const int T = in_sizes[0] / DIM;           // 65536 tokens
    const int grid = T / BLOCK_TOKENS;         // 128 blocks

    cudaFuncSetAttribute(gating_kernel,
                         cudaFuncAttributeMaxDynamicSharedMemorySize, SMEM_BYTES);
    gating_kernel<<<grid, THREADS, SMEM_BYTES>>>(x, W, b, out, T);
}

// round 3
// speedup vs baseline: 1.2444x; 1.2433x over previous
#include <cuda_runtime.h>
#include <cuda_bf16.h>
#include <cstdint>

#define NUM_EXPERTS 16
#define NPAIR 8
#define DIM 1024
#define THREADS 512
#define NWARP 16
#define GRID 148
#define DC 16                  // dims per pipeline stage
#define NSTAGE 4
#define NCH (DIM / DC)         // 64 stages of work
#define PITCH 20               // floats per token row in a stage (conflict-free)
#define TOK_PER_WARP 32

// shared memory layout (floats)
#define WS_FLOATS (NUM_EXPERTS * DIM)          // 16384, pair-major [pair][d][2]
#define B_OFF     WS_FLOATS                    // 32 floats (16 used)
#define X_OFF     (WS_FLOATS + 32)
#define STAGE_FLOATS (TOK_PER_WARP * PITCH)    // 640
#define WARP_FLOATS  (NSTAGE * STAGE_FLOATS)   // 2560
#define SMEM_FLOATS  (X_OFF + NWARP * WARP_FLOATS)   // 57376
#define SMEM_BYTES   (SMEM_FLOATS * 4)               // 229504 B

__device__ __forceinline__ void ffma2(unsigned long long& acc,
                                      unsigned long long a,
                                      unsigned long long b) {
    asm("fma.rn.f32x2 %0, %1, %2, %0;" : "+l"(acc) : "l"(a), "l"(b));
}

__device__ __forceinline__ unsigned long long pack2(float v) {
    unsigned long long r;
    asm("mov.b64 %0, {%1, %1};" : "=l"(r) : "r"(__float_as_uint(v)));
    return r;
}

__device__ __forceinline__ void stage_cp(uint32_t xbase_u32, const float* xg,
                                         int stage, int c, int lane) {
    // Copy 32 tokens x 16 dims (2KB) for this warp's tile, stage `stage`,
    // dim offset c*DC. 4 x 16B cp.async per lane, coalesced 64B per 4 lanes.
    const uint32_t dst0 = xbase_u32 + (uint32_t)(stage * STAGE_FLOATS) * 4;
#pragma unroll
    for (int k = 0; k < 4; k++) {
        int i = lane + (k << 5);
        int t = i >> 2;          // token within tile
        int j = i & 3;           // float4 within 16-dim row
        const float* src = xg + (size_t)t * DIM + c * DC + j * 4;
        uint32_t dst = dst0 + (uint32_t)(t * PITCH + j * 4) * 4;
        asm volatile("cp.async.cg.shared.global [%0], [%1], 16;\n"
                     :: "r"(dst), "l"(src));
    }
}

__global__ __launch_bounds__(THREADS, 1)
void gating_kernel(const float* __restrict__ x,
                   const float* __restrict__ W,
                   const float* __restrict__ b,
                   float* __restrict__ out,
                   int T /* total tokens */) {
    extern __shared__ float smem[];
    float* W_s = smem;
    float* b_s = smem + B_OFF;

    const int tid  = threadIdx.x;
    const int wid  = tid >> 5;
    const int lane = tid & 31;
    const int ntiles = T / TOK_PER_WARP;                 // 2048
    const int tt = blockIdx.x + (int)gridDim.x * wid;    // balanced warp-tile id
    const bool active = (tt < ntiles);

    const uint32_t smem_u32 = (uint32_t)__cvta_generic_to_shared(smem);
    const uint32_t xbase_u32 = smem_u32 + (uint32_t)(X_OFF + wid * WARP_FLOATS) * 4;
    const float* xg = x + (size_t)tt * TOK_PER_WARP * DIM;

    // Kick off the first 3 stages for active warps (writes warp-private smem,
    // safe to overlap with the W repack + barrier below).
    if (active) {
#pragma unroll
        for (int s = 0; s < NSTAGE - 1; s++) {
            stage_cp(xbase_u32, xg, s, s, lane);
            asm volatile("cp.async.commit_group;\n" ::: "memory");
        }
    }

    // Repack W into pair-major [pair][d][2] (all threads participate).
    for (int i = tid; i < NUM_EXPERTS * DIM; i += THREADS) {
        int e = i >> 10;
        int d = i & (DIM - 1);
        W_s[(((e >> 1) << 10) + d) * 2 + (e & 1)] = W[i];
    }
    if (tid < NUM_EXPERTS) b_s[tid] = b[tid];
    __syncthreads();
    if (!active) return;

    unsigned long long acc[NPAIR];
#pragma unroll
    for (int p = 0; p < NPAIR; p++) acc[p] = 0ULL;

    for (int c = 0; c < NCH; c++) {
        // Prefetch stage c+3 (empty commit when past the end keeps counts valid).
        if (c + NSTAGE - 1 < NCH) {
            stage_cp(xbase_u32, xg, (c + NSTAGE - 1) & (NSTAGE - 1),
                     c + NSTAGE - 1, lane);
        }
        asm volatile("cp.async.commit_group;\n" ::: "memory");
        // Allow 3 groups in flight -> oldest (stage c) is complete.
        asm volatile("cp.async.wait_group %0;\n" :: "n"(NSTAGE - 1) : "memory");
        __syncwarp();

        const uint32_t xrow = xbase_u32 +
            (uint32_t)((c & (NSTAGE - 1)) * STAGE_FLOATS + lane * PITCH) * 4;
#pragma unroll
        for (int j = 0; j < DC / 4; j++) {
            float x0, x1, x2, x3;
            asm("ld.shared.v4.f32 {%0, %1, %2, %3}, [%4];"
                : "=f"(x0), "=f"(x1), "=f"(x2), "=f"(x3)
                : "r"(xrow + (uint32_t)(j * 16)));
            unsigned long long xx0 = pack2(x0);
            unsigned long long xx1 = pack2(x1);
            unsigned long long xx2 = pack2(x2);
            unsigned long long xx3 = pack2(x3);
            // W address: d = c*DC + j*4, 8 bytes per (pair,d)
            const uint32_t wj = smem_u32 + (uint32_t)(c * DC + j * 4) * 8;
#pragma unroll
            for (int p = 0; p < NPAIR; p++) {
                unsigned long long w0, w1, w2, w3;
                uint32_t a = wj + (uint32_t)(p * DIM) * 8;
                asm("ld.shared.v2.b64 {%0, %1}, [%2];"
                    : "=l"(w0), "=l"(w1) : "r"(a));
                asm("ld.shared.v2.b64 {%0, %1}, [%2];"
                    : "=l"(w2), "=l"(w3) : "r"(a + 16));
                ffma2(acc[p], xx0, w0);
                ffma2(acc[p], xx1, w1);
                ffma2(acc[p], xx2, w2);
                ffma2(acc[p], xx3, w3);
            }
        }
    }

    // ---- epilogue: bias, softmax, top-2, scatter ----
    float logit[NUM_EXPERTS];
#pragma unroll
    for (int p = 0; p < NPAIR; p++) {
        logit[2 * p]     = __uint_as_float((uint32_t)acc[p]) + b_s[2 * p];
        logit[2 * p + 1] = __uint_as_float((uint32_t)(acc[p] >> 32)) + b_s[2 * p + 1];
    }

    float m = logit[0];
#pragma unroll
    for (int e = 1; e < NUM_EXPERTS; e++) m = fmaxf(m, logit[e]);

    float sum = 0.0f;
#pragma unroll
    for (int e = 0; e < NUM_EXPERTS; e++) {
        float w = __expf(logit[e] - m);
        logit[e] = w;
        sum += w;
    }
    const float inv = __fdividef(1.0f, sum);
#pragma unroll
    for (int e = 0; e < NUM_EXPERTS; e++) logit[e] *= inv;

    // top-2 (strict > keeps lowest index on ties, matching jax top_k)
    float v1 = -1.0f, v2 = -1.0f;
    int i1 = 0, i2 = 0;
#pragma unroll
    for (int e = 0; e < NUM_EXPERTS; e++) {
        float w = logit[e];
        if (w > v1) { v2 = v1; i2 = i1; v1 = w; i1 = e; }
        else if (w > v2) { v2 = w; i2 = e; }
    }

    const size_t t = (size_t)tt * TOK_PER_WARP + lane;
    float* outg = out;                                   // gated  [E, T]
    float* outw = out + (size_t)NUM_EXPERTS * T;         // weights[E, T]
#pragma unroll
    for (int e = 0; e < NUM_EXPERTS; e++) {
        float g = (e == i1) ? v1 : ((e == i2) ? v2 : 0.0f);
        outg[(size_t)e * T + t] = g;
        outw[(size_t)e * T + t] = logit[e];
    }
}

extern "C" void kernel_launch(void* const* d_in, const int* in_sizes, int n_in,
                              void* d_out, int out_size) {
    const float* x = (const float*)d_in[0];
    const float* W = (const float*)d_in[1];
    const float* b = (const float*)d_in[2];
    float* out = (float*)d_out;

    const int T = in_sizes[0] / DIM;           // 65536 tokens

    cudaFuncSetAttribute(gating_kernel,
                         cudaFuncAttributeMaxDynamicSharedMemorySize, SMEM_BYTES);
    gating_kernel<<<GRID, THREADS, SMEM_BYTES>>>(x, W, b, out, T);
}

// round 5
// speedup vs baseline: 1.5868x; 1.2751x over previous
#include <cuda_runtime.h>
#include <cuda_bf16.h>
#include <cstdint>

#define NUM_EXPERTS 16
#define DIM 1024
#define THREADS 512
#define NWARP 16
#define GRID 148
#define DC 16                  // dims per pipeline stage
#define NSTAGE 4
#define NCH (DIM / DC)         // 64 stages of work
#define PITCH 20               // floats per token row in a stage (conflict-free)
#define TOK_PER_WARP 32
#define EPITCH_B 80            // epilogue scratch row pitch (16B-aligned)

// W layout: pair-major [pair][d] of f32x2 (expert even/odd), row pitch padded
// so the 4 pair-group addresses in one LDS.128 hit distinct bank quads.
#define WPITCH_B 8224                        // 1024*8 + 32 (16B-aligned)
#define W_FLOATS (8 * WPITCH_B / 4)          // 16448
#define B_OFF    W_FLOATS                    // bias, 32 floats (16 used)
#define X_OFF    (W_FLOATS + 32)
#define STAGE_FLOATS (TOK_PER_WARP * PITCH)  // 640
#define STAGE_BYTES  (STAGE_FLOATS * 4)      // 2560
#define WARP_FLOATS  (NSTAGE * STAGE_FLOATS) // 2560
#define SMEM_FLOATS  (X_OFF + NWARP * WARP_FLOATS)   // 57440
#define SMEM_BYTES   (SMEM_FLOATS * 4)               // 229760 B

typedef unsigned long long ull;

__device__ __forceinline__ void ffma2(ull& acc, ull a, ull b) {
    asm("fma.rn.f32x2 %0, %1, %2, %0;" : "+l"(acc) : "l"(a), "l"(b));
}

__device__ __forceinline__ ull pack2(float v) {
    ull r;
    asm("mov.b64 %0, {%1, %1};" : "=l"(r) : "r"(__float_as_uint(v)));
    return r;
}

__device__ __forceinline__ void stage_cp(uint32_t xbase_u32, const float* xg,
                                         int stage, int c, int lane) {
    // 32 tokens x 16 dims (2KB) for this warp, stage `stage`, dim offset c*DC.
    const uint32_t dst0 = xbase_u32 + (uint32_t)(stage * STAGE_BYTES);
#pragma unroll
    for (int k = 0; k < 4; k++) {
        int i = lane + (k << 5);
        int t = i >> 2;          // token within tile
        int j = i & 3;           // float4 within 16-dim row
        const float* src = xg + (size_t)t * DIM + c * DC + j * 4;
        uint32_t dst = dst0 + (uint32_t)(t * PITCH + j * 4) * 4;
        asm volatile("cp.async.cg.shared.global [%0], [%1], 16;\n"
                     :: "r"(dst), "l"(src));
    }
}

__global__ __launch_bounds__(THREADS, 1)
void gating_kernel(const float* __restrict__ x,
                   const float* __restrict__ W,
                   const float* __restrict__ b,
                   float* __restrict__ out,
                   int T /* total tokens */) {
    extern __shared__ float smem[];
    float* W_s = smem;
    float* b_s = smem + B_OFF;

    const int tid  = threadIdx.x;
    const int wid  = tid >> 5;
    const int lane = tid & 31;
    const int pg   = lane >> 3;      // pair group 0..3 (owns pairs pg, pg+4)
    const int ts   = lane & 7;       // token slot (owns tokens ts+8k, k=0..3)
    const int ntiles = T / TOK_PER_WARP;                 // 2048
    const int tt = blockIdx.x + (int)gridDim.x * wid;    // balanced warp-tile id
    const bool active = (tt < ntiles);

    const uint32_t smem_u32 = (uint32_t)__cvta_generic_to_shared(smem);
    const uint32_t xbase_u32 = smem_u32 + (uint32_t)(X_OFF * 4 + wid * WARP_FLOATS * 4);
    const float* xg = x + (size_t)tt * TOK_PER_WARP * DIM;

    // Kick off first 3 stages (warp-private smem; safe across the barrier).
    if (active) {
#pragma unroll
        for (int s = 0; s < NSTAGE - 1; s++) {
            stage_cp(xbase_u32, xg, s, s, lane);
            asm volatile("cp.async.commit_group;\n" ::: "memory");
        }
    }

    // Repack W: byte addr = (e>>1)*WPITCH_B + d*8 + (e&1)*4
    for (int i = tid; i < NUM_EXPERTS * DIM; i += THREADS) {
        int e = i >> 10;
        int d = i & (DIM - 1);
        uint32_t off = (uint32_t)(e >> 1) * WPITCH_B + (uint32_t)d * 8 + (uint32_t)(e & 1) * 4;
        *reinterpret_cast<float*>(reinterpret_cast<char*>(W_s) + off) = W[i];
    }
    if (tid < NUM_EXPERTS) b_s[tid] = b[tid];
    __syncthreads();
    if (!active) return;

    const uint32_t wbaseA = smem_u32 + (uint32_t)pg * WPITCH_B;
    const uint32_t wbaseB = wbaseA + 4 * WPITCH_B;

    ull accA[4] = {0ULL, 0ULL, 0ULL, 0ULL};   // pair pg,   tokens ts+8k
    ull accB[4] = {0ULL, 0ULL, 0ULL, 0ULL};   // pair pg+4, tokens ts+8k

    for (int c = 0; c < NCH; c++) {
        if (c + NSTAGE - 1 < NCH) {
            stage_cp(xbase_u32, xg, (c + NSTAGE - 1) & (NSTAGE - 1),
                     c + NSTAGE - 1, lane);
        }
        asm volatile("cp.async.commit_group;\n" ::: "memory");
        asm volatile("cp.async.wait_group %0;\n" :: "n"(NSTAGE - 1) : "memory");
        __syncwarp();

        const uint32_t xs = xbase_u32 +
            (uint32_t)((c & (NSTAGE - 1)) * STAGE_BYTES + ts * PITCH * 4);
        const uint32_t wd = (uint32_t)c * (DC * 8);   // byte offset for dim base
#pragma unroll
        for (int j = 0; j < DC / 4; j++) {
            ull wA0, wA1, wA2, wA3, wB0, wB1, wB2, wB3;
            uint32_t wa = wbaseA + wd + (uint32_t)(j * 32);
            uint32_t wb = wbaseB + wd + (uint32_t)(j * 32);
            asm("ld.shared.v2.b64 {%0, %1}, [%2];" : "=l"(wA0), "=l"(wA1) : "r"(wa));
            asm("ld.shared.v2.b64 {%0, %1}, [%2];" : "=l"(wA2), "=l"(wA3) : "r"(wa + 16));
            asm("ld.shared.v2.b64 {%0, %1}, [%2];" : "=l"(wB0), "=l"(wB1) : "r"(wb));
            asm("ld.shared.v2.b64 {%0, %1}, [%2];" : "=l"(wB2), "=l"(wB3) : "r"(wb + 16));
#pragma unroll
            for (int k = 0; k < 4; k++) {
                float x0, x1, x2, x3;
                asm("ld.shared.v4.f32 {%0, %1, %2, %3}, [%4];"
                    : "=f"(x0), "=f"(x1), "=f"(x2), "=f"(x3)
                    : "r"(xs + (uint32_t)(k * 8 * PITCH * 4 + j * 16)));
                ull xx0 = pack2(x0);
                ull xx1 = pack2(x1);
                ull xx2 = pack2(x2);
                ull xx3 = pack2(x3);
                ffma2(accA[k], xx0, wA0);
                ffma2(accA[k], xx1, wA1);
                ffma2(accA[k], xx2, wA2);
                ffma2(accA[k], xx3, wA3);
                ffma2(accB[k], xx0, wB0);
                ffma2(accB[k], xx1, wB1);
                ffma2(accB[k], xx2, wB2);
                ffma2(accB[k], xx3, wB3);
            }
        }
    }

    // ---- epilogue: transpose acc to token-major via warp-private smem ----
    // scratch: 32 tokens x EPITCH_B(80B) rows in this warp's stage area (2560B).
    __syncwarp();
#pragma unroll
    for (int k = 0; k < 4; k++) {
        uint32_t row = xbase_u32 + (uint32_t)((ts + 8 * k) * EPITCH_B);
        asm volatile("st.shared.b64 [%0], %1;"
                     :: "r"(row + (uint32_t)(pg * 8)), "l"(accA[k]));
        asm volatile("st.shared.b64 [%0], %1;"
                     :: "r"(row + (uint32_t)((pg + 4) * 8)), "l"(accB[k]));
    }
    __syncwarp();

    float logit[NUM_EXPERTS];
    {
        uint32_t myrow = xbase_u32 + (uint32_t)(lane * EPITCH_B);
#pragma unroll
        for (int q = 0; q < 4; q++) {
            asm("ld.shared.v4.f32 {%0, %1, %2, %3}, [%4];"
                : "=f"(logit[4 * q]), "=f"(logit[4 * q + 1]),
                  "=f"(logit[4 * q + 2]), "=f"(logit[4 * q + 3])
                : "r"(myrow + (uint32_t)(q * 16)));
        }
    }
#pragma unroll
    for (int e = 0; e < NUM_EXPERTS; e++) logit[e] += b_s[e];

    float m = logit[0];
#pragma unroll
    for (int e = 1; e < NUM_EXPERTS; e++) m = fmaxf(m, logit[e]);

    float sum = 0.0f;
#pragma unroll
    for (int e = 0; e < NUM_EXPERTS; e++) {
        float w = __expf(logit[e] - m);
        logit[e] = w;
        sum += w;
    }
    const float inv = __fdividef(1.0f, sum);
#pragma unroll
    for (int e = 0; e < NUM_EXPERTS; e++) logit[e] *= inv;

    // top-2 (strict > keeps lowest index on ties, matching jax top_k)
    float v1 = -1.0f, v2 = -1.0f;
    int i1 = 0, i2 = 0;
#pragma unroll
    for (int e = 0; e < NUM_EXPERTS; e++) {
        float w = logit[e];
        if (w > v1) { v2 = v1; i2 = i1; v1 = w; i1 = e; }
        else if (w > v2) { v2 = w; i2 = e; }
    }

    const size_t t = (size_t)tt * TOK_PER_WARP + lane;
    float* outg = out;                                   // gated  [E, T]
    float* outw = out + (size_t)NUM_EXPERTS * T;         // weights[E, T]
#pragma unroll
    for (int e = 0; e < NUM_EXPERTS; e++) {
        float g = (e == i1) ? v1 : ((e == i2) ? v2 : 0.0f);
        outg[(size_t)e * T + t] = g;
        outw[(size_t)e * T + t] = logit[e];
    }
}

extern "C" void kernel_launch(void* const* d_in, const int* in_sizes, int n_in,
                              void* d_out, int out_size) {
    const float* x = (const float*)d_in[0];
    const float* W = (const float*)d_in[1];
    const float* b = (const float*)d_in[2];
    float* out = (float*)d_out;

    const int T = in_sizes[0] / DIM;           // 65536 tokens

    cudaFuncSetAttribute(gating_kernel,
                         cudaFuncAttributeMaxDynamicSharedMemorySize, SMEM_BYTES);
    gating_kernel<<<GRID, THREADS, SMEM_BYTES>>>(x, W, b, out, T);
}